// round 4
// baseline (speedup 1.0000x reference)
#include <cuda_runtime.h>
#include <cuda_fp16.h>

#define NN 100000
#define EC 6400000
#define ED 400000
#define HH 8
#define FIN 5
#define BN_EPS 1e-5
#define L2_EPS 1e-12f
#define SB 512

// ---------------- scratch ----------------
__device__ int   g_rankc[EC];
__device__ int   g_rankd[ED];
__device__ int   g_csrc[EC];                 // CSR src lists (by dst)
__device__ int   g_csrd[ED];
__device__ int   g_cntc[NN];
__device__ int   g_cntd[NN];
__device__ int   g_rowc[NN];                 // exclusive row starts
__device__ int   g_rowd[NN];
__device__ int   g_bsum[256];
__device__ __align__(16) __half g_zh[NN * HH];   // fp16 gather payload (next Wl @ h)
__device__ __align__(16) float  g_h[NN * HH];    // post-BN features
__device__ __align__(16) float  g_y[NN * HH];    // pre-BN activations
__device__ double g_stats[5 * 16];
__device__ int    g_mode;

// ---------------- init ----------------
__global__ void k_init() {
    int i = blockIdx.x * blockDim.x + threadIdx.x;
    if (i < NN) { g_cntc[i] = 0; g_cntd[i] = 0; }
    if (i < 5 * 16) g_stats[i] = 0.0;
}

// ---------------- int64 vs int32 edge dtype detection ----------------
__global__ void k_detect(const int* __restrict__ ei) {
    int lane = threadIdx.x;
    int v = ei[2 * lane + 1];
    unsigned ball = __ballot_sync(0xffffffffu, v == 0);
    if (lane == 0) g_mode = (ball == 0xffffffffu) ? 1 : 0;
}

__device__ __forceinline__ void load_edge(const void* ei, int E, int e, int& src, int& dst) {
    if (g_mode) {
        const long long* p = (const long long*)ei;
        src = (int)p[e]; dst = (int)p[E + e];
    } else {
        const int* p = (const int*)ei;
        src = p[e]; dst = p[E + e];
    }
}

// ---------------- count + rank ----------------
__global__ void k_count(const void* __restrict__ ei, int* __restrict__ cnt,
                        int* __restrict__ rank, int E) {
    int e = blockIdx.x * blockDim.x + threadIdx.x;
    if (e >= E) return;
    int src, dst; load_edge(ei, E, e, src, dst);
    rank[e] = atomicAdd(&cnt[dst], 1);
}

// ---------------- exclusive scan over NN counts ----------------
__global__ void k_scan1(const int* __restrict__ cnt, int* __restrict__ row,
                        int* __restrict__ bsum, int n) {
    __shared__ int sh[SB];
    int tid = threadIdx.x;
    int g = blockIdx.x * SB + tid;
    int v = (g < n) ? cnt[g] : 0;
    sh[tid] = v; __syncthreads();
#pragma unroll
    for (int o = 1; o < SB; o <<= 1) {
        int t = (tid >= o) ? sh[tid - o] : 0;
        __syncthreads();
        sh[tid] += t;
        __syncthreads();
    }
    if (g < n) row[g] = sh[tid] - v;          // exclusive
    if (tid == SB - 1) bsum[blockIdx.x] = sh[SB - 1];
}
__global__ void k_scan2(int* __restrict__ bsum, int nb) {
    __shared__ int sh[256];
    int tid = threadIdx.x;
    int v = (tid < nb) ? bsum[tid] : 0;
    sh[tid] = v; __syncthreads();
#pragma unroll
    for (int o = 1; o < 256; o <<= 1) {
        int t = (tid >= o) ? sh[tid - o] : 0;
        __syncthreads();
        sh[tid] += t;
        __syncthreads();
    }
    if (tid < nb) bsum[tid] = sh[tid] - v;    // exclusive
}
__global__ void k_scan3(int* __restrict__ row, const int* __restrict__ bsum, int n) {
    int g = blockIdx.x * SB + threadIdx.x;
    if (g < n) row[g] += bsum[blockIdx.x];
}

// ---------------- CSR placement ----------------
__global__ void k_place(const void* __restrict__ ei, const int* __restrict__ rank,
                        const int* __restrict__ row, int* __restrict__ csr, int E) {
    int e = blockIdx.x * blockDim.x + threadIdx.x;
    if (e >= E) return;
    int src, dst; load_edge(ei, E, e, src, dst);
    csr[row[dst] + rank[e]] = src;
}

// ---------------- z for layer 1: z = x @ W1l^T (fp16 out) ----------------
__global__ void k_z_first(const float* __restrict__ x, const float* __restrict__ W1l) {
    __shared__ float w[HH * FIN];
    if (threadIdx.x < HH * FIN) w[threadIdx.x] = W1l[threadIdx.x];
    __syncthreads();
    int i = blockIdx.x * blockDim.x + threadIdx.x;
    if (i >= NN) return;
    float xv[FIN];
#pragma unroll
    for (int f = 0; f < FIN; f++) xv[f] = x[i * FIN + f];
    float z[HH];
#pragma unroll
    for (int h = 0; h < HH; h++) {
        float s = 0.f;
#pragma unroll
        for (int f = 0; f < FIN; f++) s += xv[f] * w[h * FIN + f];
        z[h] = s;
    }
    __half2 out[4];
#pragma unroll
    for (int k = 0; k < 4; k++) out[k] = __floats2half2_rn(z[2 * k], z[2 * k + 1]);
    *(uint4*)&g_zh[i * HH] = *(uint4*)out;
}

// ---------------- partial gather: part-th thread of 4, stride-4 over row ----------------
__device__ __forceinline__ void gather_part(int s, int e, int part,
                                            const int* __restrict__ csr, float acc[HH]) {
    int p = s + part;
    // unroll-by-2: two independent edge chains in flight per thread
    for (; p + 4 < e; p += 8) {
        int s0 = __ldg(&csr[p]);
        int s1 = __ldg(&csr[p + 4]);
        uint4 a = *(const uint4*)&g_zh[s0 * HH];
        uint4 b = *(const uint4*)&g_zh[s1 * HH];
        const __half2* ah = (const __half2*)&a;
        const __half2* bh = (const __half2*)&b;
#pragma unroll
        for (int k = 0; k < 4; k++) {
            float2 fa = __half22float2(ah[k]);
            float2 fb = __half22float2(bh[k]);
            acc[2 * k]     += fa.x + fb.x;
            acc[2 * k + 1] += fa.y + fb.y;
        }
    }
    if (p < e) {
        int s0 = __ldg(&csr[p]);
        uint4 a = *(const uint4*)&g_zh[s0 * HH];
        const __half2* ah = (const __half2*)&a;
#pragma unroll
        for (int k = 0; k < 4; k++) {
            float2 fa = __half22float2(ah[k]);
            acc[2 * k]     += fa.x;
            acc[2 * k + 1] += fa.y;
        }
    }
}

// combine partial sums across 4-lane group; all lanes get the total
__device__ __forceinline__ void combine4(float acc[HH]) {
#pragma unroll
    for (int h = 0; h < HH; h++) {
        acc[h] += __shfl_xor_sync(0xffffffffu, acc[h], 1);
        acc[h] += __shfl_xor_sync(0xffffffffu, acc[h], 2);
    }
}

__device__ __forceinline__ void stats_reduce(const float out[HH], int layer, int tid) {
#pragma unroll
    for (int h = 0; h < HH; h++) {
        float s = out[h];
        float q = out[h] * out[h];
#pragma unroll
        for (int o = 16; o; o >>= 1) {
            s += __shfl_down_sync(0xffffffffu, s, o);
            q += __shfl_down_sync(0xffffffffu, q, o);
        }
        if ((tid & 31) == 0) {
            atomicAdd(&g_stats[layer * 16 + h], (double)s);
            atomicAdd(&g_stats[layer * 16 + 8 + h], (double)q);
        }
    }
}

// ---------------- layer 1: split-4 gather + node (root from x, F=5) ----------------
__global__ void k_layer_first(const float* __restrict__ x, const float* __restrict__ W1r) {
    __shared__ float w[HH * FIN];
    if (threadIdx.x < HH * FIN) w[threadIdx.x] = W1r[threadIdx.x];
    __syncthreads();
    int gid = blockIdx.x * blockDim.x + threadIdx.x;
    int i = gid >> 2;
    int part = gid & 3;
    bool act = i < NN;
    float acc[HH];
#pragma unroll
    for (int h = 0; h < HH; h++) acc[h] = 0.f;
    int d = 0;
    if (act) {
        int s = g_rowc[i]; d = g_cntc[i];
        gather_part(s, s + d, part, g_csrc, acc);
    }
    combine4(acc);
    float out[HH];
#pragma unroll
    for (int h = 0; h < HH; h++) out[h] = 0.f;
    if (act && part == 0) {
        float inv = 1.f / fmaxf((float)d, 1.f);
        float xv[FIN];
#pragma unroll
        for (int f = 0; f < FIN; f++) xv[f] = x[i * FIN + f];
        float nrm = 0.f;
#pragma unroll
        for (int h = 0; h < HH; h++) {
            float sum = acc[h] * inv;
#pragma unroll
            for (int f = 0; f < FIN; f++) sum += xv[f] * w[h * FIN + f];
            out[h] = sum;
            nrm += sum * sum;
        }
        float invn = 1.f / fmaxf(sqrtf(nrm), L2_EPS);
#pragma unroll
        for (int h = 0; h < HH; h++) {
            float v = fmaxf(out[h] * invn, 0.f);
            out[h] = v;
            g_y[i * HH + h] = v;
        }
    } else {
#pragma unroll
        for (int h = 0; h < HH; h++) out[h] = 0.f;
    }
    stats_reduce(out, 0, threadIdx.x);
}

// ---------------- layers 2..5: split-4 gather + node (root from g_h) ----------------
__global__ void k_layer(const int* __restrict__ row, const int* __restrict__ cnt,
                        const int* __restrict__ csr, const float* __restrict__ Wr, int layer) {
    __shared__ float w[HH * HH];
    if (threadIdx.x < HH * HH) w[threadIdx.x] = Wr[threadIdx.x];
    __syncthreads();
    int gid = blockIdx.x * blockDim.x + threadIdx.x;
    int i = gid >> 2;
    int part = gid & 3;
    bool act = i < NN;
    float acc[HH];
#pragma unroll
    for (int h = 0; h < HH; h++) acc[h] = 0.f;
    int d = 0;
    if (act) {
        int s = row[i]; d = cnt[i];
        gather_part(s, s + d, part, csr, acc);
    }
    combine4(acc);
    float out[HH];
#pragma unroll
    for (int h = 0; h < HH; h++) out[h] = 0.f;
    if (act && part == 0) {
        float inv = 1.f / fmaxf((float)d, 1.f);
        float hv[HH];
#pragma unroll
        for (int f = 0; f < HH; f++) hv[f] = g_h[i * HH + f];
        float nrm = 0.f;
#pragma unroll
        for (int h = 0; h < HH; h++) {
            float sum = acc[h] * inv;
#pragma unroll
            for (int f = 0; f < HH; f++) sum += hv[f] * w[h * HH + f];
            out[h] = sum;
            nrm += sum * sum;
        }
        float invn = 1.f / fmaxf(sqrtf(nrm), L2_EPS);
#pragma unroll
        for (int h = 0; h < HH; h++) {
            float v = fmaxf(out[h] * invn, 0.f);
            out[h] = v;
            g_y[i * HH + h] = v;
        }
    }
    stats_reduce(out, layer, threadIdx.x);
}

// ---------------- BN apply + next-layer z (fp16) ----------------
__global__ void k_bn(int layer, const float* __restrict__ gam, const float* __restrict__ bet,
                     const float* __restrict__ Wlnext, float* __restrict__ outp, int writeZ) {
    __shared__ float sm[HH], srs[HH], sg[HH], sb[HH], wl[HH * HH];
    int t = threadIdx.x;
    if (t < HH) {
        double s = g_stats[layer * 16 + t];
        double q = g_stats[layer * 16 + 8 + t];
        double m = s / (double)NN;
        double v = q / (double)NN - m * m;
        sm[t] = (float)m;
        srs[t] = (float)rsqrt(v + BN_EPS);
        sg[t] = gam[t];
        sb[t] = bet[t];
    }
    if (writeZ && t < HH * HH) wl[t] = Wlnext[t];
    __syncthreads();
    int i = blockIdx.x * blockDim.x + threadIdx.x;
    if (i >= NN) return;
    float hv[HH];
#pragma unroll
    for (int h = 0; h < HH; h++) {
        float v = (g_y[i * HH + h] - sm[h]) * srs[h] * sg[h] + sb[h];
        hv[h] = v;
        outp[i * HH + h] = v;
    }
    if (writeZ) {
        float z[HH];
#pragma unroll
        for (int h = 0; h < HH; h++) {
            float s = 0.f;
#pragma unroll
            for (int f = 0; f < HH; f++) s += hv[f] * wl[h * HH + f];
            z[h] = s;
        }
        __half2 zo[4];
#pragma unroll
        for (int k = 0; k < 4; k++) zo[k] = __floats2half2_rn(z[2 * k], z[2 * k + 1]);
        *(uint4*)&g_zh[i * HH] = *(uint4*)zo;
    }
}

// ---------------- host ----------------
extern "C" void kernel_launch(void* const* d_in, const int* in_sizes, int n_in,
                              void* d_out, int out_size) {
    const float* x   = (const float*)d_in[0];
    const void*  eic = d_in[1];
    const void*  eid = d_in[2];
    const float* W1l = (const float*)d_in[3];
    const float* W1r = (const float*)d_in[4];
    const float* W2l = (const float*)d_in[5];
    const float* W2r = (const float*)d_in[6];
    const float* W3l = (const float*)d_in[7];
    const float* W3r = (const float*)d_in[8];
    const float* W4l = (const float*)d_in[9];
    const float* W4r = (const float*)d_in[10];
    const float* g1 = (const float*)d_in[11]; const float* b1 = (const float*)d_in[12];
    const float* g2 = (const float*)d_in[13]; const float* b2 = (const float*)d_in[14];
    const float* g3 = (const float*)d_in[15]; const float* b3 = (const float*)d_in[16];
    const float* g4 = (const float*)d_in[17]; const float* b4 = (const float*)d_in[18];
    float* out = (float*)d_out;

    const int T = 256;
    const int gN  = (NN + T - 1) / T;
    const int gN4 = (NN * 4 + T - 1) / T;
    const int gEC = (EC + T - 1) / T;
    const int gED = (ED + T - 1) / T;
    const int nbN = (NN + SB - 1) / SB;

    int* prankc; cudaGetSymbolAddress((void**)&prankc, g_rankc);
    int* prankd; cudaGetSymbolAddress((void**)&prankd, g_rankd);
    int* pcsrc;  cudaGetSymbolAddress((void**)&pcsrc, g_csrc);
    int* pcsrd;  cudaGetSymbolAddress((void**)&pcsrd, g_csrd);
    int* pcc;    cudaGetSymbolAddress((void**)&pcc, g_cntc);
    int* pcd;    cudaGetSymbolAddress((void**)&pcd, g_cntd);
    int* prc;    cudaGetSymbolAddress((void**)&prc, g_rowc);
    int* prd;    cudaGetSymbolAddress((void**)&prd, g_rowd);
    int* pbs;    cudaGetSymbolAddress((void**)&pbs, g_bsum);
    float* ph;   cudaGetSymbolAddress((void**)&ph, g_h);

    // ---- CSR build ----
    k_init<<<gN, T>>>();
    k_detect<<<1, 32>>>((const int*)eic);
    k_count<<<gEC, T>>>(eic, pcc, prankc, EC);
    k_count<<<gED, T>>>(eid, pcd, prankd, ED);
    k_scan1<<<nbN, SB>>>(pcc, prc, pbs, NN);
    k_scan2<<<1, 256>>>(pbs, nbN);
    k_scan3<<<nbN, SB>>>(prc, pbs, NN);
    k_scan1<<<nbN, SB>>>(pcd, prd, pbs, NN);
    k_scan2<<<1, 256>>>(pbs, nbN);
    k_scan3<<<nbN, SB>>>(prd, pbs, NN);
    k_place<<<gEC, T>>>(eic, prankc, prc, pcsrc, EC);
    k_place<<<gED, T>>>(eid, prankd, prd, pcsrd, ED);
    k_z_first<<<gN, T>>>(x, W1l);

    // ---- layer 1: conv1 + bn1 (next payload W4l) ----
    k_layer_first<<<gN4, T>>>(x, W1r);
    k_bn<<<gN, T>>>(0, g1, b1, W4l, ph, 1);
    // ---- layer 2: conv4 + bn2 (next W2l) ----
    k_layer<<<gN4, T>>>(prc, pcc, pcsrc, W4r, 1);
    k_bn<<<gN, T>>>(1, g2, b2, W2l, ph, 1);
    // ---- layer 3 (destination edges): conv2 + bn3 (next W3l) ----
    k_layer<<<gN4, T>>>(prd, pcd, pcsrd, W2r, 2);
    k_bn<<<gN, T>>>(2, g3, b3, W3l, ph, 1);
    // ---- layer 4: conv3 + bn4 (next W3l) ----
    k_layer<<<gN4, T>>>(prc, pcc, pcsrc, W3r, 3);
    k_bn<<<gN, T>>>(3, g4, b4, W3l, ph, 1);
    // ---- layer 5: conv3 + bn4 -> d_out ----
    k_layer<<<gN4, T>>>(prc, pcc, pcsrc, W3r, 4);
    k_bn<<<gN, T>>>(4, g4, b4, nullptr, out, 0);
}

// round 5
// speedup vs baseline: 1.9922x; 1.9922x over previous
#include <cuda_runtime.h>
#include <cuda_fp16.h>

#define NN 100000
#define EC 6400000
#define ED 400000
#define HH 8
#define FIN 5
#define BN_EPS 1e-5
#define L2_EPS 1e-12f
#define SB 512
#define NBIN 512

// ---------------- scratch ----------------
__device__ int   g_rankc[EC];
__device__ int   g_rankd[ED];
__device__ int   g_csrc[EC];                 // CSR src lists (by dst)
__device__ int   g_csrd[ED];
__device__ int   g_cntc[NN];
__device__ int   g_cntd[NN];
__device__ int   g_rowc[NN];                 // exclusive row starts
__device__ int   g_rowd[NN];
__device__ int   g_bsum[256];
__device__ int   g_hist[NBIN];
__device__ int   g_orderc[NN];               // nodes sorted by EC degree (desc)
__device__ int   g_orderd[NN];               // nodes sorted by ED degree (desc)
__device__ __align__(16) __half g_zh[NN * HH];   // fp16 gather payload (next Wl @ h)
__device__ __align__(16) float  g_h[NN * HH];    // post-BN features
__device__ __align__(16) float  g_y[NN * HH];    // pre-BN activations
__device__ double g_stats[5 * 16];
__device__ int    g_mode;

// ---------------- init ----------------
__global__ void k_init() {
    int i = blockIdx.x * blockDim.x + threadIdx.x;
    if (i < NN) { g_cntc[i] = 0; g_cntd[i] = 0; }
    if (i < 5 * 16) g_stats[i] = 0.0;
    if (i < NBIN) g_hist[i] = 0;
}

// ---------------- int64 vs int32 edge dtype detection ----------------
__global__ void k_detect(const int* __restrict__ ei) {
    int lane = threadIdx.x;
    int v = ei[2 * lane + 1];
    unsigned ball = __ballot_sync(0xffffffffu, v == 0);
    if (lane == 0) g_mode = (ball == 0xffffffffu) ? 1 : 0;
}

__device__ __forceinline__ void load_edge(const void* ei, int E, int e, int& src, int& dst) {
    if (g_mode) {
        const long long* p = (const long long*)ei;
        src = (int)p[e]; dst = (int)p[E + e];
    } else {
        const int* p = (const int*)ei;
        src = p[e]; dst = p[E + e];
    }
}

// ---------------- count + rank ----------------
__global__ void k_count(const void* __restrict__ ei, int* __restrict__ cnt,
                        int* __restrict__ rank, int E) {
    int e = blockIdx.x * blockDim.x + threadIdx.x;
    if (e >= E) return;
    int src, dst; load_edge(ei, E, e, src, dst);
    rank[e] = atomicAdd(&cnt[dst], 1);
}

// ---------------- exclusive scan over NN counts ----------------
__global__ void k_scan1(const int* __restrict__ cnt, int* __restrict__ row,
                        int* __restrict__ bsum, int n) {
    __shared__ int sh[SB];
    int tid = threadIdx.x;
    int g = blockIdx.x * SB + tid;
    int v = (g < n) ? cnt[g] : 0;
    sh[tid] = v; __syncthreads();
#pragma unroll
    for (int o = 1; o < SB; o <<= 1) {
        int t = (tid >= o) ? sh[tid - o] : 0;
        __syncthreads();
        sh[tid] += t;
        __syncthreads();
    }
    if (g < n) row[g] = sh[tid] - v;          // exclusive
    if (tid == SB - 1) bsum[blockIdx.x] = sh[SB - 1];
}
__global__ void k_scan2(int* __restrict__ bsum, int nb) {
    __shared__ int sh[256];
    int tid = threadIdx.x;
    int v = (tid < nb) ? bsum[tid] : 0;
    sh[tid] = v; __syncthreads();
#pragma unroll
    for (int o = 1; o < 256; o <<= 1) {
        int t = (tid >= o) ? sh[tid - o] : 0;
        __syncthreads();
        sh[tid] += t;
        __syncthreads();
    }
    if (tid < nb) bsum[tid] = sh[tid] - v;    // exclusive
}
__global__ void k_scan3(int* __restrict__ row, const int* __restrict__ bsum, int n) {
    int g = blockIdx.x * SB + threadIdx.x;
    if (g < n) row[g] += bsum[blockIdx.x];
}

// ---------------- CSR placement ----------------
__global__ void k_place(const void* __restrict__ ei, const int* __restrict__ rank,
                        const int* __restrict__ row, int* __restrict__ csr, int E) {
    int e = blockIdx.x * blockDim.x + threadIdx.x;
    if (e >= E) return;
    int src, dst; load_edge(ei, E, e, src, dst);
    csr[row[dst] + rank[e]] = src;
}

// ---------------- degree counting-sort (descending) ----------------
__device__ __forceinline__ int deg_bin(int d) {
    d = d < NBIN - 1 ? d : NBIN - 1;
    return (NBIN - 1) - d;       // descending degree order
}
__global__ void k_hist_zero() { g_hist[threadIdx.x] = 0; }
__global__ void k_hist(const int* __restrict__ cnt) {
    int i = blockIdx.x * blockDim.x + threadIdx.x;
    if (i < NN) atomicAdd(&g_hist[deg_bin(cnt[i])], 1);
}
__global__ void k_scan512() {                // in-place exclusive scan of g_hist
    __shared__ int sh[NBIN];
    int t = threadIdx.x;
    int v = g_hist[t];
    sh[t] = v; __syncthreads();
#pragma unroll
    for (int o = 1; o < NBIN; o <<= 1) {
        int u = (t >= o) ? sh[t - o] : 0;
        __syncthreads();
        sh[t] += u;
        __syncthreads();
    }
    g_hist[t] = sh[t] - v;
}
__global__ void k_order(const int* __restrict__ cnt, int* __restrict__ order) {
    int i = blockIdx.x * blockDim.x + threadIdx.x;
    if (i < NN) order[atomicAdd(&g_hist[deg_bin(cnt[i])], 1)] = i;
}

// ---------------- z for layer 1: z = x @ W1l^T (fp16 out) ----------------
__global__ void k_z_first(const float* __restrict__ x, const float* __restrict__ W1l) {
    __shared__ float w[HH * FIN];
    if (threadIdx.x < HH * FIN) w[threadIdx.x] = W1l[threadIdx.x];
    __syncthreads();
    int i = blockIdx.x * blockDim.x + threadIdx.x;
    if (i >= NN) return;
    float xv[FIN];
#pragma unroll
    for (int f = 0; f < FIN; f++) xv[f] = x[i * FIN + f];
    float z[HH];
#pragma unroll
    for (int h = 0; h < HH; h++) {
        float s = 0.f;
#pragma unroll
        for (int f = 0; f < FIN; f++) s += xv[f] * w[h * FIN + f];
        z[h] = s;
    }
    __half2 out[4];
#pragma unroll
    for (int k = 0; k < 4; k++) out[k] = __floats2half2_rn(z[2 * k], z[2 * k + 1]);
    *(uint4*)&g_zh[i * HH] = *(uint4*)out;
}

// ---------------- gather acc = sum_{src in row} z[src] (round-2 proven form) --------
__device__ __forceinline__ void gather_row(int s, int d, const int* __restrict__ csr,
                                           float acc[HH]) {
    int e = s + d;
    int p = s;
    for (; p + 1 < e; p += 2) {
        int s0 = __ldg(&csr[p]);
        int s1 = __ldg(&csr[p + 1]);
        uint4 a = *(const uint4*)&g_zh[s0 * HH];
        uint4 b = *(const uint4*)&g_zh[s1 * HH];
        const __half2* ah = (const __half2*)&a;
        const __half2* bh = (const __half2*)&b;
#pragma unroll
        for (int k = 0; k < 4; k++) {
            float2 fa = __half22float2(ah[k]);
            float2 fb = __half22float2(bh[k]);
            acc[2 * k]     += fa.x + fb.x;
            acc[2 * k + 1] += fa.y + fb.y;
        }
    }
    if (p < e) {
        int s0 = __ldg(&csr[p]);
        uint4 a = *(const uint4*)&g_zh[s0 * HH];
        const __half2* ah = (const __half2*)&a;
#pragma unroll
        for (int k = 0; k < 4; k++) {
            float2 fa = __half22float2(ah[k]);
            acc[2 * k]     += fa.x;
            acc[2 * k + 1] += fa.y;
        }
    }
}

__device__ __forceinline__ void stats_reduce(const float out[HH], int layer, int tid) {
#pragma unroll
    for (int h = 0; h < HH; h++) {
        float s = out[h];
        float q = out[h] * out[h];
#pragma unroll
        for (int o = 16; o; o >>= 1) {
            s += __shfl_down_sync(0xffffffffu, s, o);
            q += __shfl_down_sync(0xffffffffu, q, o);
        }
        if ((tid & 31) == 0) {
            atomicAdd(&g_stats[layer * 16 + h], (double)s);
            atomicAdd(&g_stats[layer * 16 + 8 + h], (double)q);
        }
    }
}

__device__ __forceinline__ void finish_node(float out[HH], int i) {
    float nrm = 0.f;
#pragma unroll
    for (int h = 0; h < HH; h++) nrm += out[h] * out[h];
    float invn = 1.f / fmaxf(sqrtf(nrm), L2_EPS);
#pragma unroll
    for (int h = 0; h < HH; h++) {
        float v = fmaxf(out[h] * invn, 0.f);
        out[h] = v;
        g_y[i * HH + h] = v;
    }
}

// ---------------- layer 1: gather + node (root from x, F=5), degree-ordered --------
__global__ void k_layer_first(const float* __restrict__ x, const float* __restrict__ W1r) {
    __shared__ float w[HH * FIN];
    if (threadIdx.x < HH * FIN) w[threadIdx.x] = W1r[threadIdx.x];
    __syncthreads();
    int t = blockIdx.x * blockDim.x + threadIdx.x;
    bool act = t < NN;
    int i = act ? g_orderc[t] : 0;
    float out[HH];
#pragma unroll
    for (int h = 0; h < HH; h++) out[h] = 0.f;
    if (act) {
        int s = g_rowc[i], d = g_cntc[i];
        float acc[HH];
#pragma unroll
        for (int h = 0; h < HH; h++) acc[h] = 0.f;
        gather_row(s, d, g_csrc, acc);
        float inv = 1.f / fmaxf((float)d, 1.f);
        float xv[FIN];
#pragma unroll
        for (int f = 0; f < FIN; f++) xv[f] = x[i * FIN + f];
#pragma unroll
        for (int h = 0; h < HH; h++) {
            float sum = acc[h] * inv;
#pragma unroll
            for (int f = 0; f < FIN; f++) sum += xv[f] * w[h * FIN + f];
            out[h] = sum;
        }
        finish_node(out, i);
    }
    stats_reduce(out, 0, threadIdx.x);
}

// ---------------- layers 2..5: gather + node (root from g_h), degree-ordered -------
__global__ void k_layer(const int* __restrict__ row, const int* __restrict__ cnt,
                        const int* __restrict__ csr, const int* __restrict__ order,
                        const float* __restrict__ Wr, int layer) {
    __shared__ float w[HH * HH];
    if (threadIdx.x < HH * HH) w[threadIdx.x] = Wr[threadIdx.x];
    __syncthreads();
    int t = blockIdx.x * blockDim.x + threadIdx.x;
    bool act = t < NN;
    int i = act ? order[t] : 0;
    float out[HH];
#pragma unroll
    for (int h = 0; h < HH; h++) out[h] = 0.f;
    if (act) {
        int s = row[i], d = cnt[i];
        float acc[HH];
#pragma unroll
        for (int h = 0; h < HH; h++) acc[h] = 0.f;
        gather_row(s, d, csr, acc);
        float inv = 1.f / fmaxf((float)d, 1.f);
        float hv[HH];
#pragma unroll
        for (int f = 0; f < HH; f++) hv[f] = g_h[i * HH + f];
#pragma unroll
        for (int h = 0; h < HH; h++) {
            float sum = acc[h] * inv;
#pragma unroll
            for (int f = 0; f < HH; f++) sum += hv[f] * w[h * HH + f];
            out[h] = sum;
        }
        finish_node(out, i);
    }
    stats_reduce(out, layer, threadIdx.x);
}

// ---------------- BN apply + next-layer z (fp16) ----------------
__global__ void k_bn(int layer, const float* __restrict__ gam, const float* __restrict__ bet,
                     const float* __restrict__ Wlnext, float* __restrict__ outp, int writeZ) {
    __shared__ float sm[HH], srs[HH], sg[HH], sb[HH], wl[HH * HH];
    int t = threadIdx.x;
    if (t < HH) {
        double s = g_stats[layer * 16 + t];
        double q = g_stats[layer * 16 + 8 + t];
        double m = s / (double)NN;
        double v = q / (double)NN - m * m;
        sm[t] = (float)m;
        srs[t] = (float)rsqrt(v + BN_EPS);
        sg[t] = gam[t];
        sb[t] = bet[t];
    }
    if (writeZ && t < HH * HH) wl[t] = Wlnext[t];
    __syncthreads();
    int i = blockIdx.x * blockDim.x + threadIdx.x;
    if (i >= NN) return;
    float hv[HH];
#pragma unroll
    for (int h = 0; h < HH; h++) {
        float v = (g_y[i * HH + h] - sm[h]) * srs[h] * sg[h] + sb[h];
        hv[h] = v;
        outp[i * HH + h] = v;
    }
    if (writeZ) {
        float z[HH];
#pragma unroll
        for (int h = 0; h < HH; h++) {
            float s = 0.f;
#pragma unroll
            for (int f = 0; f < HH; f++) s += hv[f] * wl[h * HH + f];
            z[h] = s;
        }
        __half2 zo[4];
#pragma unroll
        for (int k = 0; k < 4; k++) zo[k] = __floats2half2_rn(z[2 * k], z[2 * k + 1]);
        *(uint4*)&g_zh[i * HH] = *(uint4*)zo;
    }
}

// ---------------- host ----------------
extern "C" void kernel_launch(void* const* d_in, const int* in_sizes, int n_in,
                              void* d_out, int out_size) {
    const float* x   = (const float*)d_in[0];
    const void*  eic = d_in[1];
    const void*  eid = d_in[2];
    const float* W1l = (const float*)d_in[3];
    const float* W1r = (const float*)d_in[4];
    const float* W2l = (const float*)d_in[5];
    const float* W2r = (const float*)d_in[6];
    const float* W3l = (const float*)d_in[7];
    const float* W3r = (const float*)d_in[8];
    const float* W4l = (const float*)d_in[9];
    const float* W4r = (const float*)d_in[10];
    const float* g1 = (const float*)d_in[11]; const float* b1 = (const float*)d_in[12];
    const float* g2 = (const float*)d_in[13]; const float* b2 = (const float*)d_in[14];
    const float* g3 = (const float*)d_in[15]; const float* b3 = (const float*)d_in[16];
    const float* g4 = (const float*)d_in[17]; const float* b4 = (const float*)d_in[18];
    float* out = (float*)d_out;

    const int T = 256;
    const int gN  = (NN + T - 1) / T;
    const int gEC = (EC + T - 1) / T;
    const int gED = (ED + T - 1) / T;
    const int nbN = (NN + SB - 1) / SB;

    int* prankc; cudaGetSymbolAddress((void**)&prankc, g_rankc);
    int* prankd; cudaGetSymbolAddress((void**)&prankd, g_rankd);
    int* pcsrc;  cudaGetSymbolAddress((void**)&pcsrc, g_csrc);
    int* pcsrd;  cudaGetSymbolAddress((void**)&pcsrd, g_csrd);
    int* pcc;    cudaGetSymbolAddress((void**)&pcc, g_cntc);
    int* pcd;    cudaGetSymbolAddress((void**)&pcd, g_cntd);
    int* prc;    cudaGetSymbolAddress((void**)&prc, g_rowc);
    int* prd;    cudaGetSymbolAddress((void**)&prd, g_rowd);
    int* pbs;    cudaGetSymbolAddress((void**)&pbs, g_bsum);
    int* poc;    cudaGetSymbolAddress((void**)&poc, g_orderc);
    int* pod;    cudaGetSymbolAddress((void**)&pod, g_orderd);
    float* ph;   cudaGetSymbolAddress((void**)&ph, g_h);

    // ---- CSR build ----
    k_init<<<gN, T>>>();
    k_detect<<<1, 32>>>((const int*)eic);
    k_count<<<gEC, T>>>(eic, pcc, prankc, EC);
    k_count<<<gED, T>>>(eid, pcd, prankd, ED);
    k_scan1<<<nbN, SB>>>(pcc, prc, pbs, NN);
    k_scan2<<<1, 256>>>(pbs, nbN);
    k_scan3<<<nbN, SB>>>(prc, pbs, NN);
    k_scan1<<<nbN, SB>>>(pcd, prd, pbs, NN);
    k_scan2<<<1, 256>>>(pbs, nbN);
    k_scan3<<<nbN, SB>>>(prd, pbs, NN);
    k_place<<<gEC, T>>>(eic, prankc, prc, pcsrc, EC);
    k_place<<<gED, T>>>(eid, prankd, prd, pcsrd, ED);

    // ---- degree-order (counting sort, descending) ----
    k_hist<<<gN, T>>>(pcc);            // g_hist zeroed in k_init
    k_scan512<<<1, NBIN>>>();
    k_order<<<gN, T>>>(pcc, poc);
    k_hist_zero<<<1, NBIN>>>();
    k_hist<<<gN, T>>>(pcd);
    k_scan512<<<1, NBIN>>>();
    k_order<<<gN, T>>>(pcd, pod);

    k_z_first<<<gN, T>>>(x, W1l);

    // ---- layer 1: conv1 + bn1 (next payload W4l) ----
    k_layer_first<<<gN, T>>>(x, W1r);
    k_bn<<<gN, T>>>(0, g1, b1, W4l, ph, 1);
    // ---- layer 2: conv4 + bn2 (next W2l) ----
    k_layer<<<gN, T>>>(prc, pcc, pcsrc, poc, W4r, 1);
    k_bn<<<gN, T>>>(1, g2, b2, W2l, ph, 1);
    // ---- layer 3 (destination edges): conv2 + bn3 (next W3l) ----
    k_layer<<<gN, T>>>(prd, pcd, pcsrd, pod, W2r, 2);
    k_bn<<<gN, T>>>(2, g3, b3, W3l, ph, 1);
    // ---- layer 4: conv3 + bn4 (next W3l) ----
    k_layer<<<gN, T>>>(prc, pcc, pcsrc, poc, W3r, 3);
    k_bn<<<gN, T>>>(3, g4, b4, W3l, ph, 1);
    // ---- layer 5: conv3 + bn4 -> d_out ----
    k_layer<<<gN, T>>>(prc, pcc, pcsrc, poc, W3r, 4);
    k_bn<<<gN, T>>>(4, g4, b4, nullptr, out, 0);
}

// round 6
// speedup vs baseline: 3.2586x; 1.6357x over previous
#include <cuda_runtime.h>
#include <cuda_fp16.h>

#define NN 100000
#define EC 6400000
#define ED 400000
#define HH 8
#define FIN 5
#define BN_EPS 1e-5
#define L2_EPS 1e-12f
#define SB 512

// ---------------- scratch ----------------
__device__ int   g_csrc[EC];                 // CSR src lists (by dst)
__device__ int   g_csrd[ED];
__device__ int   g_cntc[NN];
__device__ int   g_cntd[NN];
__device__ int   g_curc[NN];                 // placement cursors
__device__ int   g_curd[NN];
__device__ int   g_rowc[NN];                 // exclusive row starts
__device__ int   g_rowd[NN];
__device__ int   g_bsum[256];
__device__ __align__(16) __half g_zh[NN * HH];   // fp16 gather payload (next Wl @ h)
__device__ __align__(16) float  g_h[NN * HH];    // post-BN features
__device__ __align__(16) float  g_y[NN * HH];    // pre-BN activations
__device__ double g_stats[5 * 16];
__device__ int    g_mode;

// ---------------- init ----------------
__global__ void k_init() {
    int i = blockIdx.x * blockDim.x + threadIdx.x;
    if (i < NN) { g_cntc[i] = 0; g_cntd[i] = 0; g_curc[i] = 0; g_curd[i] = 0; }
    if (i < 5 * 16) g_stats[i] = 0.0;
}

// ---------------- int64 vs int32 edge dtype detection ----------------
__global__ void k_detect(const int* __restrict__ ei) {
    int lane = threadIdx.x;
    int v = ei[2 * lane + 1];
    unsigned ball = __ballot_sync(0xffffffffu, v == 0);
    if (lane == 0) g_mode = (ball == 0xffffffffu) ? 1 : 0;
}

__device__ __forceinline__ void load_edge(const void* ei, int E, int e, int& src, int& dst) {
    if (g_mode) {
        const long long* p = (const long long*)ei;
        src = (int)p[e]; dst = (int)p[E + e];
    } else {
        const int* p = (const int*)ei;
        src = p[e]; dst = p[E + e];
    }
}

// ---------------- count (no rank stored) ----------------
__global__ void k_count(const void* __restrict__ ei, int* __restrict__ cnt, int E) {
    int e = blockIdx.x * blockDim.x + threadIdx.x;
    if (e >= E) return;
    int src, dst; load_edge(ei, E, e, src, dst);
    atomicAdd(&cnt[dst], 1);
}

// ---------------- exclusive scan over NN counts ----------------
__global__ void k_scan1(const int* __restrict__ cnt, int* __restrict__ row,
                        int* __restrict__ bsum, int n) {
    __shared__ int sh[SB];
    int tid = threadIdx.x;
    int g = blockIdx.x * SB + tid;
    int v = (g < n) ? cnt[g] : 0;
    sh[tid] = v; __syncthreads();
#pragma unroll
    for (int o = 1; o < SB; o <<= 1) {
        int t = (tid >= o) ? sh[tid - o] : 0;
        __syncthreads();
        sh[tid] += t;
        __syncthreads();
    }
    if (g < n) row[g] = sh[tid] - v;          // exclusive
    if (tid == SB - 1) bsum[blockIdx.x] = sh[SB - 1];
}
__global__ void k_scan2(int* __restrict__ bsum, int nb) {
    __shared__ int sh[256];
    int tid = threadIdx.x;
    int v = (tid < nb) ? bsum[tid] : 0;
    sh[tid] = v; __syncthreads();
#pragma unroll
    for (int o = 1; o < 256; o <<= 1) {
        int t = (tid >= o) ? sh[tid - o] : 0;
        __syncthreads();
        sh[tid] += t;
        __syncthreads();
    }
    if (tid < nb) bsum[tid] = sh[tid] - v;    // exclusive
}
__global__ void k_scan3(int* __restrict__ row, const int* __restrict__ bsum, int n) {
    int g = blockIdx.x * SB + threadIdx.x;
    if (g < n) row[g] += bsum[blockIdx.x];
}

// ---------------- CSR placement (cursor atomic; row order is irrelevant for sums) --
__global__ void k_place(const void* __restrict__ ei, int* __restrict__ cur,
                        const int* __restrict__ row, int* __restrict__ csr, int E) {
    int e = blockIdx.x * blockDim.x + threadIdx.x;
    if (e >= E) return;
    int src, dst; load_edge(ei, E, e, src, dst);
    int pos = row[dst] + atomicAdd(&cur[dst], 1);
    csr[pos] = src;
}

// ---------------- z for layer 1: z = x @ W1l^T (fp16 out) ----------------
__global__ void k_z_first(const float* __restrict__ x, const float* __restrict__ W1l) {
    __shared__ float w[HH * FIN];
    if (threadIdx.x < HH * FIN) w[threadIdx.x] = W1l[threadIdx.x];
    __syncthreads();
    int i = blockIdx.x * blockDim.x + threadIdx.x;
    if (i >= NN) return;
    float xv[FIN];
#pragma unroll
    for (int f = 0; f < FIN; f++) xv[f] = x[i * FIN + f];
    float z[HH];
#pragma unroll
    for (int h = 0; h < HH; h++) {
        float s = 0.f;
#pragma unroll
        for (int f = 0; f < FIN; f++) s += xv[f] * w[h * FIN + f];
        z[h] = s;
    }
    __half2 out[4];
#pragma unroll
    for (int k = 0; k < 4; k++) out[k] = __floats2half2_rn(z[2 * k], z[2 * k + 1]);
    *(uint4*)&g_zh[i * HH] = *(uint4*)out;
}

// ---------------- add one fp16x8 payload into acc ----------------
__device__ __forceinline__ void acc_payload(const uint4& a, float acc[HH]) {
    const __half2* ah = (const __half2*)&a;
#pragma unroll
    for (int k = 0; k < 4; k++) {
        float2 fa = __half22float2(ah[k]);
        acc[2 * k]     += fa.x;
        acc[2 * k + 1] += fa.y;
    }
}

// ---------------- gather acc = sum_{src in row} z[src], unroll-4 ----------------
__device__ __forceinline__ void gather_row(int s, int d, const int* __restrict__ csr,
                                           float acc[HH]) {
    int e = s + d;
    int p = s;
    for (; p + 3 < e; p += 4) {
        int s0 = __ldg(&csr[p]);
        int s1 = __ldg(&csr[p + 1]);
        int s2 = __ldg(&csr[p + 2]);
        int s3 = __ldg(&csr[p + 3]);
        uint4 a0 = __ldg((const uint4*)&g_zh[s0 * HH]);
        uint4 a1 = __ldg((const uint4*)&g_zh[s1 * HH]);
        uint4 a2 = __ldg((const uint4*)&g_zh[s2 * HH]);
        uint4 a3 = __ldg((const uint4*)&g_zh[s3 * HH]);
        acc_payload(a0, acc);
        acc_payload(a1, acc);
        acc_payload(a2, acc);
        acc_payload(a3, acc);
    }
    for (; p < e; p++) {
        int s0 = __ldg(&csr[p]);
        uint4 a0 = __ldg((const uint4*)&g_zh[s0 * HH]);
        acc_payload(a0, acc);
    }
}

// ---------------- block-level BN stats: warp shuffle -> smem -> 16 dbl atomics ----
__device__ __forceinline__ void stats_block(const float out[HH], int layer,
                                            float* sstat) {
    int tid = threadIdx.x;
#pragma unroll
    for (int h = 0; h < HH; h++) {
        float s = out[h];
        float q = out[h] * out[h];
#pragma unroll
        for (int o = 16; o; o >>= 1) {
            s += __shfl_down_sync(0xffffffffu, s, o);
            q += __shfl_down_sync(0xffffffffu, q, o);
        }
        if ((tid & 31) == 0) {
            atomicAdd(&sstat[h], s);
            atomicAdd(&sstat[8 + h], q);
        }
    }
    __syncthreads();
    if (tid < 16) atomicAdd(&g_stats[layer * 16 + tid], (double)sstat[tid]);
}

__device__ __forceinline__ void finish_node(float out[HH], int i) {
    float nrm = 0.f;
#pragma unroll
    for (int h = 0; h < HH; h++) nrm += out[h] * out[h];
    float invn = 1.f / fmaxf(sqrtf(nrm), L2_EPS);
#pragma unroll
    for (int h = 0; h < HH; h++) {
        float v = fmaxf(out[h] * invn, 0.f);
        out[h] = v;
        g_y[i * HH + h] = v;
    }
}

// ---------------- layer 1: gather + node (root from x, F=5) ----------------
__global__ void k_layer_first(const float* __restrict__ x, const float* __restrict__ W1r) {
    __shared__ float w[HH * FIN];
    __shared__ float sstat[16];
    if (threadIdx.x < HH * FIN) w[threadIdx.x] = W1r[threadIdx.x];
    if (threadIdx.x < 16) sstat[threadIdx.x] = 0.f;
    __syncthreads();
    int i = blockIdx.x * blockDim.x + threadIdx.x;
    bool act = i < NN;
    float out[HH];
#pragma unroll
    for (int h = 0; h < HH; h++) out[h] = 0.f;
    if (act) {
        int s = g_rowc[i], d = g_cntc[i];
        float acc[HH];
#pragma unroll
        for (int h = 0; h < HH; h++) acc[h] = 0.f;
        gather_row(s, d, g_csrc, acc);
        float inv = 1.f / fmaxf((float)d, 1.f);
        float xv[FIN];
#pragma unroll
        for (int f = 0; f < FIN; f++) xv[f] = x[i * FIN + f];
#pragma unroll
        for (int h = 0; h < HH; h++) {
            float sum = acc[h] * inv;
#pragma unroll
            for (int f = 0; f < FIN; f++) sum += xv[f] * w[h * FIN + f];
            out[h] = sum;
        }
        finish_node(out, i);
    }
    stats_block(out, 0, sstat);
}

// ---------------- layers 2..5: gather + node (root from g_h) ----------------
__global__ void k_layer(const int* __restrict__ row, const int* __restrict__ cnt,
                        const int* __restrict__ csr, const float* __restrict__ Wr, int layer) {
    __shared__ float w[HH * HH];
    __shared__ float sstat[16];
    if (threadIdx.x < HH * HH) w[threadIdx.x] = Wr[threadIdx.x];
    if (threadIdx.x < 16) sstat[threadIdx.x] = 0.f;
    __syncthreads();
    int i = blockIdx.x * blockDim.x + threadIdx.x;
    bool act = i < NN;
    float out[HH];
#pragma unroll
    for (int h = 0; h < HH; h++) out[h] = 0.f;
    if (act) {
        int s = row[i], d = cnt[i];
        float acc[HH];
#pragma unroll
        for (int h = 0; h < HH; h++) acc[h] = 0.f;
        gather_row(s, d, csr, acc);
        float inv = 1.f / fmaxf((float)d, 1.f);
        float hv[HH];
#pragma unroll
        for (int f = 0; f < HH; f++) hv[f] = g_h[i * HH + f];
#pragma unroll
        for (int h = 0; h < HH; h++) {
            float sum = acc[h] * inv;
#pragma unroll
            for (int f = 0; f < HH; f++) sum += hv[f] * w[h * HH + f];
            out[h] = sum;
        }
        finish_node(out, i);
    }
    stats_block(out, layer, sstat);
}

// ---------------- BN apply + next-layer z (fp16) ----------------
__global__ void k_bn(int layer, const float* __restrict__ gam, const float* __restrict__ bet,
                     const float* __restrict__ Wlnext, float* __restrict__ outp, int writeZ) {
    __shared__ float sm[HH], srs[HH], sg[HH], sb[HH], wl[HH * HH];
    int t = threadIdx.x;
    if (t < HH) {
        double s = g_stats[layer * 16 + t];
        double q = g_stats[layer * 16 + 8 + t];
        double m = s / (double)NN;
        double v = q / (double)NN - m * m;
        sm[t] = (float)m;
        srs[t] = (float)rsqrt(v + BN_EPS);
        sg[t] = gam[t];
        sb[t] = bet[t];
    }
    if (writeZ && t < HH * HH) wl[t] = Wlnext[t];
    __syncthreads();
    int i = blockIdx.x * blockDim.x + threadIdx.x;
    if (i >= NN) return;
    float hv[HH];
#pragma unroll
    for (int h = 0; h < HH; h++) {
        float v = (g_y[i * HH + h] - sm[h]) * srs[h] * sg[h] + sb[h];
        hv[h] = v;
        outp[i * HH + h] = v;
    }
    if (writeZ) {
        float z[HH];
#pragma unroll
        for (int h = 0; h < HH; h++) {
            float s = 0.f;
#pragma unroll
            for (int f = 0; f < HH; f++) s += hv[f] * wl[h * HH + f];
            z[h] = s;
        }
        __half2 zo[4];
#pragma unroll
        for (int k = 0; k < 4; k++) zo[k] = __floats2half2_rn(z[2 * k], z[2 * k + 1]);
        *(uint4*)&g_zh[i * HH] = *(uint4*)zo;
    }
}

// ---------------- host ----------------
extern "C" void kernel_launch(void* const* d_in, const int* in_sizes, int n_in,
                              void* d_out, int out_size) {
    const float* x   = (const float*)d_in[0];
    const void*  eic = d_in[1];
    const void*  eid = d_in[2];
    const float* W1l = (const float*)d_in[3];
    const float* W1r = (const float*)d_in[4];
    const float* W2l = (const float*)d_in[5];
    const float* W2r = (const float*)d_in[6];
    const float* W3l = (const float*)d_in[7];
    const float* W3r = (const float*)d_in[8];
    const float* W4l = (const float*)d_in[9];
    const float* W4r = (const float*)d_in[10];
    const float* g1 = (const float*)d_in[11]; const float* b1 = (const float*)d_in[12];
    const float* g2 = (const float*)d_in[13]; const float* b2 = (const float*)d_in[14];
    const float* g3 = (const float*)d_in[15]; const float* b3 = (const float*)d_in[16];
    const float* g4 = (const float*)d_in[17]; const float* b4 = (const float*)d_in[18];
    float* out = (float*)d_out;

    const int T = 256;
    const int gN  = (NN + T - 1) / T;
    const int gEC = (EC + T - 1) / T;
    const int gED = (ED + T - 1) / T;
    const int nbN = (NN + SB - 1) / SB;

    int* pcsrc;  cudaGetSymbolAddress((void**)&pcsrc, g_csrc);
    int* pcsrd;  cudaGetSymbolAddress((void**)&pcsrd, g_csrd);
    int* pcc;    cudaGetSymbolAddress((void**)&pcc, g_cntc);
    int* pcd;    cudaGetSymbolAddress((void**)&pcd, g_cntd);
    int* puc;    cudaGetSymbolAddress((void**)&puc, g_curc);
    int* pud;    cudaGetSymbolAddress((void**)&pud, g_curd);
    int* prc;    cudaGetSymbolAddress((void**)&prc, g_rowc);
    int* prd;    cudaGetSymbolAddress((void**)&prd, g_rowd);
    int* pbs;    cudaGetSymbolAddress((void**)&pbs, g_bsum);
    float* ph;   cudaGetSymbolAddress((void**)&ph, g_h);

    // ---- CSR build ----
    k_init<<<gN, T>>>();
    k_detect<<<1, 32>>>((const int*)eic);
    k_count<<<gEC, T>>>(eic, pcc, EC);
    k_count<<<gED, T>>>(eid, pcd, ED);
    k_scan1<<<nbN, SB>>>(pcc, prc, pbs, NN);
    k_scan2<<<1, 256>>>(pbs, nbN);
    k_scan3<<<nbN, SB>>>(prc, pbs, NN);
    k_scan1<<<nbN, SB>>>(pcd, prd, pbs, NN);
    k_scan2<<<1, 256>>>(pbs, nbN);
    k_scan3<<<nbN, SB>>>(prd, pbs, NN);
    k_place<<<gEC, T>>>(eic, puc, prc, pcsrc, EC);
    k_place<<<gED, T>>>(eid, pud, prd, pcsrd, ED);
    k_z_first<<<gN, T>>>(x, W1l);

    // ---- layer 1: conv1 + bn1 (next payload W4l) ----
    k_layer_first<<<gN, T>>>(x, W1r);
    k_bn<<<gN, T>>>(0, g1, b1, W4l, ph, 1);
    // ---- layer 2: conv4 + bn2 (next W2l) ----
    k_layer<<<gN, T>>>(prc, pcc, pcsrc, W4r, 1);
    k_bn<<<gN, T>>>(1, g2, b2, W2l, ph, 1);
    // ---- layer 3 (destination edges): conv2 + bn3 (next W3l) ----
    k_layer<<<gN, T>>>(prd, pcd, pcsrd, W2r, 2);
    k_bn<<<gN, T>>>(2, g3, b3, W3l, ph, 1);
    // ---- layer 4: conv3 + bn4 (next W3l) ----
    k_layer<<<gN, T>>>(prc, pcc, pcsrc, W3r, 3);
    k_bn<<<gN, T>>>(3, g4, b4, W3l, ph, 1);
    // ---- layer 5: conv3 + bn4 -> d_out ----
    k_layer<<<gN, T>>>(prc, pcc, pcsrc, W3r, 4);
    k_bn<<<gN, T>>>(4, g4, b4, nullptr, out, 0);
}

// round 7
// speedup vs baseline: 3.3567x; 1.0301x over previous
#include <cuda_runtime.h>
#include <cuda_fp16.h>

#define NN 100000
#define EC 6400000
#define ED 400000
#define HH 8
#define FIN 5
#define BN_EPS 1e-5
#define L2_EPS 1e-12f
#define SB 512
// padded CSR capacity: every row rounded up to multiple of 4
#define ECP (EC + 4 * NN)
#define EDP (ED + 4 * NN)

// ---------------- scratch ----------------
__device__ __align__(16) int g_csrc[ECP];    // padded CSR src lists (by dst)
__device__ __align__(16) int g_csrd[EDP];
__device__ int   g_cntc[NN];                 // true degrees
__device__ int   g_cntd[NN];
__device__ int   g_curc[NN];                 // placement cursors
__device__ int   g_curd[NN];
__device__ int   g_rowc[NN];                 // exclusive row starts (padded, 4-aligned)
__device__ int   g_rowd[NN];
__device__ int   g_bsum[256];
__device__ __align__(16) __half g_zh[(NN + 1) * HH]; // fp16 payload; slot NN = zero sentinel
__device__ __align__(16) float  g_h[NN * HH];    // post-BN features
__device__ __align__(16) float  g_y[NN * HH];    // pre-BN activations
__device__ double g_stats[5 * 16];
__device__ int    g_mode;

// ---------------- init ----------------
__global__ void k_init() {
    int i = blockIdx.x * blockDim.x + threadIdx.x;
    if (i < NN) { g_cntc[i] = 0; g_cntd[i] = 0; g_curc[i] = 0; g_curd[i] = 0; }
    if (i < 5 * 16) g_stats[i] = 0.0;
    if (i < HH) g_zh[NN * HH + i] = __float2half(0.f);   // zero sentinel payload
}

// ---------------- int64 vs int32 edge dtype detection ----------------
__global__ void k_detect(const int* __restrict__ ei) {
    int lane = threadIdx.x;
    int v = ei[2 * lane + 1];
    unsigned ball = __ballot_sync(0xffffffffu, v == 0);
    if (lane == 0) g_mode = (ball == 0xffffffffu) ? 1 : 0;
}

__device__ __forceinline__ void load_edge(const void* ei, int E, int e, int& src, int& dst) {
    if (g_mode) {
        const long long* p = (const long long*)ei;
        src = (int)p[e]; dst = (int)p[E + e];
    } else {
        const int* p = (const int*)ei;
        src = p[e]; dst = p[E + e];
    }
}

// ---------------- count ----------------
__global__ void k_count(const void* __restrict__ ei, int* __restrict__ cnt, int E) {
    int e = blockIdx.x * blockDim.x + threadIdx.x;
    if (e >= E) return;
    int src, dst; load_edge(ei, E, e, src, dst);
    atomicAdd(&cnt[dst], 1);
}

// ---------------- exclusive scan over padded counts ----------------
__global__ void k_scan1(const int* __restrict__ cnt, int* __restrict__ row,
                        int* __restrict__ bsum, int n) {
    __shared__ int sh[SB];
    int tid = threadIdx.x;
    int g = blockIdx.x * SB + tid;
    int v = (g < n) ? ((cnt[g] + 3) & ~3) : 0;     // padded to multiple of 4
    sh[tid] = v; __syncthreads();
#pragma unroll
    for (int o = 1; o < SB; o <<= 1) {
        int t = (tid >= o) ? sh[tid - o] : 0;
        __syncthreads();
        sh[tid] += t;
        __syncthreads();
    }
    if (g < n) row[g] = sh[tid] - v;          // exclusive
    if (tid == SB - 1) bsum[blockIdx.x] = sh[SB - 1];
}
__global__ void k_scan2(int* __restrict__ bsum, int nb) {
    __shared__ int sh[256];
    int tid = threadIdx.x;
    int v = (tid < nb) ? bsum[tid] : 0;
    sh[tid] = v; __syncthreads();
#pragma unroll
    for (int o = 1; o < 256; o <<= 1) {
        int t = (tid >= o) ? sh[tid - o] : 0;
        __syncthreads();
        sh[tid] += t;
        __syncthreads();
    }
    if (tid < nb) bsum[tid] = sh[tid] - v;    // exclusive
}
__global__ void k_scan3(int* __restrict__ row, const int* __restrict__ bsum, int n) {
    int g = blockIdx.x * SB + threadIdx.x;
    if (g < n) row[g] += bsum[blockIdx.x];
}

// ---------------- CSR placement (order within row irrelevant for sums) ----------
__global__ void k_place(const void* __restrict__ ei, int* __restrict__ cur,
                        const int* __restrict__ row, int* __restrict__ csr, int E) {
    int e = blockIdx.x * blockDim.x + threadIdx.x;
    if (e >= E) return;
    int src, dst; load_edge(ei, E, e, src, dst);
    int pos = row[dst] + atomicAdd(&cur[dst], 1);
    csr[pos] = src;
}

// ---------------- fill padding slots with zero-sentinel ----------------
__global__ void k_fill(const int* __restrict__ cnt, const int* __restrict__ row,
                       int* __restrict__ csr) {
    int i = blockIdx.x * blockDim.x + threadIdx.x;
    if (i >= NN) return;
    int d = cnt[i];
    int pad = (d + 3) & ~3;
    int s = row[i];
    for (int j = d; j < pad; j++) csr[s + j] = NN;
}

// ---------------- z for layer 1: z = x @ W1l^T (fp16 out) ----------------
__global__ void k_z_first(const float* __restrict__ x, const float* __restrict__ W1l) {
    __shared__ float w[HH * FIN];
    if (threadIdx.x < HH * FIN) w[threadIdx.x] = W1l[threadIdx.x];
    __syncthreads();
    int i = blockIdx.x * blockDim.x + threadIdx.x;
    if (i >= NN) return;
    float xv[FIN];
#pragma unroll
    for (int f = 0; f < FIN; f++) xv[f] = x[i * FIN + f];
    float z[HH];
#pragma unroll
    for (int h = 0; h < HH; h++) {
        float s = 0.f;
#pragma unroll
        for (int f = 0; f < FIN; f++) s += xv[f] * w[h * FIN + f];
        z[h] = s;
    }
    __half2 out[4];
#pragma unroll
    for (int k = 0; k < 4; k++) out[k] = __floats2half2_rn(z[2 * k], z[2 * k + 1]);
    *(uint4*)&g_zh[i * HH] = *(uint4*)out;
}

// ---------------- add one fp16x8 payload into acc ----------------
__device__ __forceinline__ void acc_payload(const uint4& a, float acc[HH]) {
    const __half2* ah = (const __half2*)&a;
#pragma unroll
    for (int k = 0; k < 4; k++) {
        float2 fa = __half22float2(ah[k]);
        acc[2 * k]     += fa.x;
        acc[2 * k + 1] += fa.y;
    }
}

// ---------------- gather: padded row, pure int4 index loads ----------------
__device__ __forceinline__ void gather_row(int s, int d, const int* __restrict__ csr,
                                           float acc[HH]) {
    int n4 = (d + 3) >> 2;
    const int4* ip = (const int4*)(csr + s);   // s is 4-aligned by construction
    for (int t = 0; t < n4; t++) {
        int4 id = __ldg(ip + t);
        uint4 a0 = __ldg((const uint4*)&g_zh[id.x * HH]);
        uint4 a1 = __ldg((const uint4*)&g_zh[id.y * HH]);
        uint4 a2 = __ldg((const uint4*)&g_zh[id.z * HH]);
        uint4 a3 = __ldg((const uint4*)&g_zh[id.w * HH]);
        acc_payload(a0, acc);
        acc_payload(a1, acc);
        acc_payload(a2, acc);
        acc_payload(a3, acc);
    }
}

// ---------------- block-level BN stats ----------------
__device__ __forceinline__ void stats_block(const float out[HH], int layer,
                                            float* sstat) {
    int tid = threadIdx.x;
#pragma unroll
    for (int h = 0; h < HH; h++) {
        float s = out[h];
        float q = out[h] * out[h];
#pragma unroll
        for (int o = 16; o; o >>= 1) {
            s += __shfl_down_sync(0xffffffffu, s, o);
            q += __shfl_down_sync(0xffffffffu, q, o);
        }
        if ((tid & 31) == 0) {
            atomicAdd(&sstat[h], s);
            atomicAdd(&sstat[8 + h], q);
        }
    }
    __syncthreads();
    if (tid < 16) atomicAdd(&g_stats[layer * 16 + tid], (double)sstat[tid]);
}

__device__ __forceinline__ void finish_node(float out[HH], int i) {
    float nrm = 0.f;
#pragma unroll
    for (int h = 0; h < HH; h++) nrm += out[h] * out[h];
    float invn = 1.f / fmaxf(sqrtf(nrm), L2_EPS);
#pragma unroll
    for (int h = 0; h < HH; h++) {
        float v = fmaxf(out[h] * invn, 0.f);
        out[h] = v;
        g_y[i * HH + h] = v;
    }
}

// ---------------- layer 1: gather + node (root from x, F=5) ----------------
__global__ void k_layer_first(const float* __restrict__ x, const float* __restrict__ W1r) {
    __shared__ float w[HH * FIN];
    __shared__ float sstat[16];
    if (threadIdx.x < HH * FIN) w[threadIdx.x] = W1r[threadIdx.x];
    if (threadIdx.x < 16) sstat[threadIdx.x] = 0.f;
    __syncthreads();
    int i = blockIdx.x * blockDim.x + threadIdx.x;
    bool act = i < NN;
    float out[HH];
#pragma unroll
    for (int h = 0; h < HH; h++) out[h] = 0.f;
    if (act) {
        int s = g_rowc[i], d = g_cntc[i];
        float acc[HH];
#pragma unroll
        for (int h = 0; h < HH; h++) acc[h] = 0.f;
        gather_row(s, d, g_csrc, acc);
        float inv = 1.f / fmaxf((float)d, 1.f);
        float xv[FIN];
#pragma unroll
        for (int f = 0; f < FIN; f++) xv[f] = x[i * FIN + f];
#pragma unroll
        for (int h = 0; h < HH; h++) {
            float sum = acc[h] * inv;
#pragma unroll
            for (int f = 0; f < FIN; f++) sum += xv[f] * w[h * FIN + f];
            out[h] = sum;
        }
        finish_node(out, i);
    }
    stats_block(out, 0, sstat);
}

// ---------------- layers 2..5: gather + node (root from g_h) ----------------
__global__ void k_layer(const int* __restrict__ row, const int* __restrict__ cnt,
                        const int* __restrict__ csr, const float* __restrict__ Wr, int layer) {
    __shared__ float w[HH * HH];
    __shared__ float sstat[16];
    if (threadIdx.x < HH * HH) w[threadIdx.x] = Wr[threadIdx.x];
    if (threadIdx.x < 16) sstat[threadIdx.x] = 0.f;
    __syncthreads();
    int i = blockIdx.x * blockDim.x + threadIdx.x;
    bool act = i < NN;
    float out[HH];
#pragma unroll
    for (int h = 0; h < HH; h++) out[h] = 0.f;
    if (act) {
        int s = row[i], d = cnt[i];
        float acc[HH];
#pragma unroll
        for (int h = 0; h < HH; h++) acc[h] = 0.f;
        gather_row(s, d, csr, acc);
        float inv = 1.f / fmaxf((float)d, 1.f);
        float hv[HH];
#pragma unroll
        for (int f = 0; f < HH; f++) hv[f] = g_h[i * HH + f];
#pragma unroll
        for (int h = 0; h < HH; h++) {
            float sum = acc[h] * inv;
#pragma unroll
            for (int f = 0; f < HH; f++) sum += hv[f] * w[h * HH + f];
            out[h] = sum;
        }
        finish_node(out, i);
    }
    stats_block(out, layer, sstat);
}

// ---------------- BN apply + next-layer z (fp16) ----------------
__global__ void k_bn(int layer, const float* __restrict__ gam, const float* __restrict__ bet,
                     const float* __restrict__ Wlnext, float* __restrict__ outp, int writeZ) {
    __shared__ float sm[HH], srs[HH], sg[HH], sb[HH], wl[HH * HH];
    int t = threadIdx.x;
    if (t < HH) {
        double s = g_stats[layer * 16 + t];
        double q = g_stats[layer * 16 + 8 + t];
        double m = s / (double)NN;
        double v = q / (double)NN - m * m;
        sm[t] = (float)m;
        srs[t] = (float)rsqrt(v + BN_EPS);
        sg[t] = gam[t];
        sb[t] = bet[t];
    }
    if (writeZ && t < HH * HH) wl[t] = Wlnext[t];
    __syncthreads();
    int i = blockIdx.x * blockDim.x + threadIdx.x;
    if (i >= NN) return;
    float hv[HH];
#pragma unroll
    for (int h = 0; h < HH; h++) {
        float v = (g_y[i * HH + h] - sm[h]) * srs[h] * sg[h] + sb[h];
        hv[h] = v;
        outp[i * HH + h] = v;
    }
    if (writeZ) {
        float z[HH];
#pragma unroll
        for (int h = 0; h < HH; h++) {
            float s = 0.f;
#pragma unroll
            for (int f = 0; f < HH; f++) s += hv[f] * wl[h * HH + f];
            z[h] = s;
        }
        __half2 zo[4];
#pragma unroll
        for (int k = 0; k < 4; k++) zo[k] = __floats2half2_rn(z[2 * k], z[2 * k + 1]);
        *(uint4*)&g_zh[i * HH] = *(uint4*)zo;
    }
}

// ---------------- host ----------------
extern "C" void kernel_launch(void* const* d_in, const int* in_sizes, int n_in,
                              void* d_out, int out_size) {
    const float* x   = (const float*)d_in[0];
    const void*  eic = d_in[1];
    const void*  eid = d_in[2];
    const float* W1l = (const float*)d_in[3];
    const float* W1r = (const float*)d_in[4];
    const float* W2l = (const float*)d_in[5];
    const float* W2r = (const float*)d_in[6];
    const float* W3l = (const float*)d_in[7];
    const float* W3r = (const float*)d_in[8];
    const float* W4l = (const float*)d_in[9];
    const float* W4r = (const float*)d_in[10];
    const float* g1 = (const float*)d_in[11]; const float* b1 = (const float*)d_in[12];
    const float* g2 = (const float*)d_in[13]; const float* b2 = (const float*)d_in[14];
    const float* g3 = (const float*)d_in[15]; const float* b3 = (const float*)d_in[16];
    const float* g4 = (const float*)d_in[17]; const float* b4 = (const float*)d_in[18];
    float* out = (float*)d_out;

    const int T = 256;
    const int gN  = (NN + T - 1) / T;
    const int gEC = (EC + T - 1) / T;
    const int gED = (ED + T - 1) / T;
    const int nbN = (NN + SB - 1) / SB;

    int* pcsrc;  cudaGetSymbolAddress((void**)&pcsrc, g_csrc);
    int* pcsrd;  cudaGetSymbolAddress((void**)&pcsrd, g_csrd);
    int* pcc;    cudaGetSymbolAddress((void**)&pcc, g_cntc);
    int* pcd;    cudaGetSymbolAddress((void**)&pcd, g_cntd);
    int* puc;    cudaGetSymbolAddress((void**)&puc, g_curc);
    int* pud;    cudaGetSymbolAddress((void**)&pud, g_curd);
    int* prc;    cudaGetSymbolAddress((void**)&prc, g_rowc);
    int* prd;    cudaGetSymbolAddress((void**)&prd, g_rowd);
    int* pbs;    cudaGetSymbolAddress((void**)&pbs, g_bsum);
    float* ph;   cudaGetSymbolAddress((void**)&ph, g_h);

    // ---- CSR build (padded rows) ----
    k_init<<<gN, T>>>();
    k_detect<<<1, 32>>>((const int*)eic);
    k_count<<<gEC, T>>>(eic, pcc, EC);
    k_count<<<gED, T>>>(eid, pcd, ED);
    k_scan1<<<nbN, SB>>>(pcc, prc, pbs, NN);
    k_scan2<<<1, 256>>>(pbs, nbN);
    k_scan3<<<nbN, SB>>>(prc, pbs, NN);
    k_scan1<<<nbN, SB>>>(pcd, prd, pbs, NN);
    k_scan2<<<1, 256>>>(pbs, nbN);
    k_scan3<<<nbN, SB>>>(prd, pbs, NN);
    k_place<<<gEC, T>>>(eic, puc, prc, pcsrc, EC);
    k_place<<<gED, T>>>(eid, pud, prd, pcsrd, ED);
    k_fill<<<gN, T>>>(pcc, prc, pcsrc);
    k_fill<<<gN, T>>>(pcd, prd, pcsrd);
    k_z_first<<<gN, T>>>(x, W1l);

    // ---- layer 1: conv1 + bn1 (next payload W4l) ----
    k_layer_first<<<gN, T>>>(x, W1r);
    k_bn<<<gN, T>>>(0, g1, b1, W4l, ph, 1);
    // ---- layer 2: conv4 + bn2 (next W2l) ----
    k_layer<<<gN, T>>>(prc, pcc, pcsrc, W4r, 1);
    k_bn<<<gN, T>>>(1, g2, b2, W2l, ph, 1);
    // ---- layer 3 (destination edges): conv2 + bn3 (next W3l) ----
    k_layer<<<gN, T>>>(prd, pcd, pcsrd, W2r, 2);
    k_bn<<<gN, T>>>(2, g3, b3, W3l, ph, 1);
    // ---- layer 4: conv3 + bn4 (next W3l) ----
    k_layer<<<gN, T>>>(prc, pcc, pcsrc, W3r, 3);
    k_bn<<<gN, T>>>(3, g4, b4, W3l, ph, 1);
    // ---- layer 5: conv3 + bn4 -> d_out ----
    k_layer<<<gN, T>>>(prc, pcc, pcsrc, W3r, 4);
    k_bn<<<gN, T>>>(4, g4, b4, nullptr, out, 0);
}

// round 8
// speedup vs baseline: 3.5711x; 1.0639x over previous
#include <cuda_runtime.h>
#include <cuda_fp16.h>

#define NN 100000
#define EC 6400000
#define ED 400000
#define HH 8
#define FIN 5
#define BN_EPS 1e-5
#define L2_EPS 1e-12f
#define SB 512
#define ECP (EC + 4 * NN)
#define EDP (ED + 4 * NN)
#define NSLICE 8

// ---------------- scratch ----------------
__device__ __align__(16) int g_csrc[ECP];    // padded CSR src lists (by dst)
__device__ __align__(16) int g_csrd[EDP];
__device__ int   g_cntc[NN];
__device__ int   g_cntd[NN];
__device__ int   g_curc[NN];
__device__ int   g_curd[NN];
__device__ int   g_rowc[NN];                 // padded, 4-aligned row starts
__device__ int   g_rowd[NN];
__device__ int   g_bsumc[256];
__device__ int   g_bsumd[256];
__device__ __align__(16) __half g_zh[(NN + 1) * HH]; // fp16 payload; slot NN = zero sentinel
__device__ __align__(16) float  g_h[NN * HH];        // post-BN features
__device__ double   g_stats[5][NSLICE][16];          // sliced BN stat accumulators
__device__ unsigned g_arrive[5];                     // grid-sync counters
__device__ int      g_mode;

// ---------------- init ----------------
__global__ void k_init() {
    int i = blockIdx.x * blockDim.x + threadIdx.x;
    if (i < NN) { g_cntc[i] = 0; g_cntd[i] = 0; g_curc[i] = 0; g_curd[i] = 0; }
    if (i < 5 * NSLICE * 16) ((double*)g_stats)[i] = 0.0;
    if (i < 5) g_arrive[i] = 0u;
    if (i < HH) g_zh[NN * HH + i] = __float2half(0.f);
}

// ---------------- int64 vs int32 edge dtype detection ----------------
__global__ void k_detect(const int* __restrict__ ei) {
    int lane = threadIdx.x;
    int v = ei[2 * lane + 1];
    unsigned ball = __ballot_sync(0xffffffffu, v == 0);
    if (lane == 0) g_mode = (ball == 0xffffffffu) ? 1 : 0;
}

__device__ __forceinline__ void load_edge(const void* ei, int E, int e, int& src, int& dst) {
    if (g_mode) {
        const long long* p = (const long long*)ei;
        src = (int)p[e]; dst = (int)p[E + e];
    } else {
        const int* p = (const int*)ei;
        src = p[e]; dst = p[E + e];
    }
}

// ---------------- fused count over both edge sets ----------------
__global__ void k_count(const void* __restrict__ eic, const void* __restrict__ eid, int gEC) {
    long long b = blockIdx.x;
    if (b < gEC) {
        int e = (int)(b * blockDim.x + threadIdx.x);
        if (e < EC) {
            int src, dst; load_edge(eic, EC, e, src, dst);
            atomicAdd(&g_cntc[dst], 1);
        }
    } else {
        int e = (int)((b - gEC) * blockDim.x + threadIdx.x);
        if (e < ED) {
            int src, dst; load_edge(eid, ED, e, src, dst);
            atomicAdd(&g_cntd[dst], 1);
        }
    }
}

// ---------------- fused scans (padded counts; c in first half of grid, d in second) --
__global__ void k_scan1() {
    __shared__ int sh[SB];
    int half = gridDim.x >> 1;
    bool isC = blockIdx.x < half;
    const int* cnt = isC ? g_cntc : g_cntd;
    int* rowp = isC ? g_rowc : g_rowd;
    int* bsum = isC ? g_bsumc : g_bsumd;
    int b = isC ? blockIdx.x : blockIdx.x - half;
    int tid = threadIdx.x;
    int g = b * SB + tid;
    int v = (g < NN) ? ((cnt[g] + 3) & ~3) : 0;
    sh[tid] = v; __syncthreads();
#pragma unroll
    for (int o = 1; o < SB; o <<= 1) {
        int t = (tid >= o) ? sh[tid - o] : 0;
        __syncthreads();
        sh[tid] += t;
        __syncthreads();
    }
    if (g < NN) rowp[g] = sh[tid] - v;
    if (tid == SB - 1) bsum[b] = sh[SB - 1];
}
__global__ void k_scan2(int nb) {
    __shared__ int sh[256];
    int* bsum = (blockIdx.x == 0) ? g_bsumc : g_bsumd;
    int tid = threadIdx.x;
    int v = (tid < nb) ? bsum[tid] : 0;
    sh[tid] = v; __syncthreads();
#pragma unroll
    for (int o = 1; o < 256; o <<= 1) {
        int t = (tid >= o) ? sh[tid - o] : 0;
        __syncthreads();
        sh[tid] += t;
        __syncthreads();
    }
    if (tid < nb) bsum[tid] = sh[tid] - v;
}
__global__ void k_scan3() {
    int half = gridDim.x >> 1;
    bool isC = blockIdx.x < half;
    int* rowp = isC ? g_rowc : g_rowd;
    const int* bsum = isC ? g_bsumc : g_bsumd;
    int b = isC ? blockIdx.x : blockIdx.x - half;
    int g = b * SB + threadIdx.x;
    if (g < NN) rowp[g] += bsum[b];
}

// ---------------- fused CSR placement ----------------
__global__ void k_place(const void* __restrict__ eic, const void* __restrict__ eid, int gEC) {
    long long b = blockIdx.x;
    if (b < gEC) {
        int e = (int)(b * blockDim.x + threadIdx.x);
        if (e < EC) {
            int src, dst; load_edge(eic, EC, e, src, dst);
            g_csrc[g_rowc[dst] + atomicAdd(&g_curc[dst], 1)] = src;
        }
    } else {
        int e = (int)((b - gEC) * blockDim.x + threadIdx.x);
        if (e < ED) {
            int src, dst; load_edge(eid, ED, e, src, dst);
            g_csrd[g_rowd[dst] + atomicAdd(&g_curd[dst], 1)] = src;
        }
    }
}

// ---------------- fill padding with zero-sentinel (both CSRs) ----------------
__global__ void k_fill(int gN) {
    int b = blockIdx.x;
    bool isC = b < gN;
    int i = (isC ? b : b - gN) * blockDim.x + threadIdx.x;
    if (i >= NN) return;
    const int* cnt = isC ? g_cntc : g_cntd;
    const int* rowp = isC ? g_rowc : g_rowd;
    int* csr = isC ? g_csrc : g_csrd;
    int d = cnt[i];
    int pad = (d + 3) & ~3;
    int s = rowp[i];
    for (int j = d; j < pad; j++) csr[s + j] = NN;
}

// ---------------- z for layer 1: z = x @ W1l^T (fp16 out) ----------------
__global__ void k_z_first(const float* __restrict__ x, const float* __restrict__ W1l) {
    __shared__ float w[HH * FIN];
    if (threadIdx.x < HH * FIN) w[threadIdx.x] = W1l[threadIdx.x];
    __syncthreads();
    int i = blockIdx.x * blockDim.x + threadIdx.x;
    if (i >= NN) return;
    float xv[FIN];
#pragma unroll
    for (int f = 0; f < FIN; f++) xv[f] = x[i * FIN + f];
    float z[HH];
#pragma unroll
    for (int h = 0; h < HH; h++) {
        float s = 0.f;
#pragma unroll
        for (int f = 0; f < FIN; f++) s += xv[f] * w[h * FIN + f];
        z[h] = s;
    }
    __half2 out[4];
#pragma unroll
    for (int k = 0; k < 4; k++) out[k] = __floats2half2_rn(z[2 * k], z[2 * k + 1]);
    *(uint4*)&g_zh[i * HH] = *(uint4*)out;
}

// ---------------- gather helpers ----------------
__device__ __forceinline__ void acc_payload(const uint4& a, float acc[HH]) {
    const __half2* ah = (const __half2*)&a;
#pragma unroll
    for (int k = 0; k < 4; k++) {
        float2 fa = __half22float2(ah[k]);
        acc[2 * k]     += fa.x;
        acc[2 * k + 1] += fa.y;
    }
}

__device__ __forceinline__ void gather_row(int s, int d, const int* __restrict__ csr,
                                           float acc[HH]) {
    int n4 = (d + 3) >> 2;
    const int4* ip = (const int4*)(csr + s);   // 4-aligned by construction
    for (int t = 0; t < n4; t++) {
        int4 id = __ldg(ip + t);
        uint4 a0 = __ldg((const uint4*)&g_zh[id.x * HH]);
        uint4 a1 = __ldg((const uint4*)&g_zh[id.y * HH]);
        uint4 a2 = __ldg((const uint4*)&g_zh[id.z * HH]);
        uint4 a3 = __ldg((const uint4*)&g_zh[id.w * HH]);
        acc_payload(a0, acc);
        acc_payload(a1, acc);
        acc_payload(a2, acc);
        acc_payload(a3, acc);
    }
}

// ---------------- block stats -> sliced global doubles ----------------
__device__ __forceinline__ void stats_block(const float out[HH], int layer, float* sstat) {
    int tid = threadIdx.x;
#pragma unroll
    for (int h = 0; h < HH; h++) {
        float s = out[h];
        float q = out[h] * out[h];
#pragma unroll
        for (int o = 16; o; o >>= 1) {
            s += __shfl_down_sync(0xffffffffu, s, o);
            q += __shfl_down_sync(0xffffffffu, q, o);
        }
        if ((tid & 31) == 0) {
            atomicAdd(&sstat[h], s);
            atomicAdd(&sstat[8 + h], q);
        }
    }
    __syncthreads();
    if (tid < 16) {
        atomicAdd(&g_stats[layer][blockIdx.x & (NSLICE - 1)][tid], (double)sstat[tid]);
        __threadfence();
    }
}

// ---------------- software grid sync (all blocks resident: 391 <= 148*8) ----------
__device__ __forceinline__ void grid_sync(int layer) {
    __syncthreads();
    if (threadIdx.x == 0) {
        atomicAdd(&g_arrive[layer], 1u);
        while (*(volatile unsigned*)&g_arrive[layer] < gridDim.x) {}
        __threadfence();
    }
    __syncthreads();
}

// ---------------- BN finalize from sliced stats into smem[16]: mean | rsqrt(var) ----
__device__ __forceinline__ void bn_params(int layer, float* sbn, double* sd) {
    int tid = threadIdx.x;
    if (tid < 16) {
        double s = 0.0;
#pragma unroll
        for (int k = 0; k < NSLICE; k++) s += g_stats[layer][k][tid];
        sd[tid] = s;
    }
    __syncthreads();
    if (tid < 8) {
        double m = sd[tid] / (double)NN;
        double v = sd[8 + tid] / (double)NN - m * m;
        sbn[tid] = (float)m;
        sbn[8 + tid] = (float)rsqrt(v + BN_EPS);
    }
    __syncthreads();
}

// l2-normalize + relu in registers
__device__ __forceinline__ void norm_relu(float out[HH]) {
    float nrm = 0.f;
#pragma unroll
    for (int h = 0; h < HH; h++) nrm += out[h] * out[h];
    float invn = 1.f / fmaxf(sqrtf(nrm), L2_EPS);
#pragma unroll
    for (int h = 0; h < HH; h++) out[h] = fmaxf(out[h] * invn, 0.f);
}

// BN-apply + write outp + optional next-z, all from registers
__device__ __forceinline__ void apply_tail(const float out[HH], int i, const float* sbn,
                                           const float* sg, const float* sb, const float* wl,
                                           float* __restrict__ outp, int writeZ) {
    float hv[HH];
#pragma unroll
    for (int h = 0; h < HH; h++)
        hv[h] = (out[h] - sbn[h]) * sbn[8 + h] * sg[h] + sb[h];
    *(float4*)&outp[i * HH]     = make_float4(hv[0], hv[1], hv[2], hv[3]);
    *(float4*)&outp[i * HH + 4] = make_float4(hv[4], hv[5], hv[6], hv[7]);
    if (writeZ) {
        float z[HH];
#pragma unroll
        for (int h = 0; h < HH; h++) {
            float s = 0.f;
#pragma unroll
            for (int f = 0; f < HH; f++) s += hv[f] * wl[h * HH + f];
            z[h] = s;
        }
        __half2 zo[4];
#pragma unroll
        for (int k = 0; k < 4; k++) zo[k] = __floats2half2_rn(z[2 * k], z[2 * k + 1]);
        *(uint4*)&g_zh[i * HH] = *(uint4*)zo;
    }
}

// ---------------- fused layer 1 (root from x, F=5) ----------------
__global__ void __launch_bounds__(256) k_layer_first(
    const float* __restrict__ x, const float* __restrict__ W1r,
    const float* __restrict__ gam, const float* __restrict__ bet,
    const float* __restrict__ Wlnext, float* __restrict__ outp)
{
    __shared__ float w[HH * FIN], wl[HH * HH], sstat[16], sg[HH], sb[HH], sbn[16];
    __shared__ double sd[16];
    int tid = threadIdx.x;
    if (tid < HH * FIN) w[tid] = W1r[tid];
    if (tid < HH * HH) wl[tid] = Wlnext[tid];
    if (tid < 16) sstat[tid] = 0.f;
    if (tid < HH) { sg[tid] = gam[tid]; sb[tid] = bet[tid]; }
    __syncthreads();
    int i = blockIdx.x * blockDim.x + tid;
    bool act = i < NN;
    float out[HH];
#pragma unroll
    for (int h = 0; h < HH; h++) out[h] = 0.f;
    if (act) {
        int s = g_rowc[i], d = g_cntc[i];
        float acc[HH];
#pragma unroll
        for (int h = 0; h < HH; h++) acc[h] = 0.f;
        gather_row(s, d, g_csrc, acc);
        float inv = 1.f / fmaxf((float)d, 1.f);
        float xv[FIN];
#pragma unroll
        for (int f = 0; f < FIN; f++) xv[f] = x[i * FIN + f];
#pragma unroll
        for (int h = 0; h < HH; h++) {
            float sum = acc[h] * inv;
#pragma unroll
            for (int f = 0; f < FIN; f++) sum += xv[f] * w[h * FIN + f];
            out[h] = sum;
        }
        norm_relu(out);
    }
    stats_block(out, 0, sstat);
    grid_sync(0);
    bn_params(0, sbn, sd);
    if (act) apply_tail(out, i, sbn, sg, sb, wl, outp, 1);
}

// ---------------- fused layers 2..5 (root from g_h) ----------------
__global__ void __launch_bounds__(256) k_layer(
    const int* __restrict__ row, const int* __restrict__ cnt, const int* __restrict__ csr,
    const float* __restrict__ Wr, const float* __restrict__ gam, const float* __restrict__ bet,
    const float* __restrict__ Wlnext, float* __restrict__ outp, int layer, int writeZ)
{
    __shared__ float w[HH * HH], wl[HH * HH], sstat[16], sg[HH], sb[HH], sbn[16];
    __shared__ double sd[16];
    int tid = threadIdx.x;
    if (tid < HH * HH) w[tid] = Wr[tid];
    if (writeZ && tid < HH * HH) wl[tid] = Wlnext[tid];
    if (tid < 16) sstat[tid] = 0.f;
    if (tid < HH) { sg[tid] = gam[tid]; sb[tid] = bet[tid]; }
    __syncthreads();
    int i = blockIdx.x * blockDim.x + tid;
    bool act = i < NN;
    float out[HH];
#pragma unroll
    for (int h = 0; h < HH; h++) out[h] = 0.f;
    if (act) {
        int s = row[i], d = cnt[i];
        float acc[HH];
#pragma unroll
        for (int h = 0; h < HH; h++) acc[h] = 0.f;
        gather_row(s, d, csr, acc);
        float inv = 1.f / fmaxf((float)d, 1.f);
        float hv[HH];
#pragma unroll
        for (int f = 0; f < HH; f++) hv[f] = g_h[i * HH + f];
#pragma unroll
        for (int h = 0; h < HH; h++) {
            float sum = acc[h] * inv;
#pragma unroll
            for (int f = 0; f < HH; f++) sum += hv[f] * w[h * HH + f];
            out[h] = sum;
        }
        norm_relu(out);
    }
    stats_block(out, layer, sstat);
    grid_sync(layer);
    bn_params(layer, sbn, sd);
    if (act) apply_tail(out, i, sbn, sg, sb, wl, outp, writeZ);
}

// ---------------- host ----------------
extern "C" void kernel_launch(void* const* d_in, const int* in_sizes, int n_in,
                              void* d_out, int out_size) {
    const float* x   = (const float*)d_in[0];
    const void*  eic = d_in[1];
    const void*  eid = d_in[2];
    const float* W1l = (const float*)d_in[3];
    const float* W1r = (const float*)d_in[4];
    const float* W2l = (const float*)d_in[5];
    const float* W2r = (const float*)d_in[6];
    const float* W3l = (const float*)d_in[7];
    const float* W3r = (const float*)d_in[8];
    const float* W4l = (const float*)d_in[9];
    const float* W4r = (const float*)d_in[10];
    const float* g1 = (const float*)d_in[11]; const float* b1 = (const float*)d_in[12];
    const float* g2 = (const float*)d_in[13]; const float* b2 = (const float*)d_in[14];
    const float* g3 = (const float*)d_in[15]; const float* b3 = (const float*)d_in[16];
    const float* g4 = (const float*)d_in[17]; const float* b4 = (const float*)d_in[18];
    float* out = (float*)d_out;

    const int T = 256;
    const int gN  = (NN + T - 1) / T;
    const int gEC = (EC + T - 1) / T;
    const int gED = (ED + T - 1) / T;
    const int nbN = (NN + SB - 1) / SB;

    int* prc;   cudaGetSymbolAddress((void**)&prc, g_rowc);
    int* prd;   cudaGetSymbolAddress((void**)&prd, g_rowd);
    int* pcc;   cudaGetSymbolAddress((void**)&pcc, g_cntc);
    int* pcd;   cudaGetSymbolAddress((void**)&pcd, g_cntd);
    int* pcsrc; cudaGetSymbolAddress((void**)&pcsrc, g_csrc);
    int* pcsrd; cudaGetSymbolAddress((void**)&pcsrd, g_csrd);
    float* ph;  cudaGetSymbolAddress((void**)&ph, g_h);

    // ---- CSR build (padded rows), fused across edge sets ----
    k_init<<<gN, T>>>();
    k_detect<<<1, 32>>>((const int*)eic);
    k_count<<<gEC + gED, T>>>(eic, eid, gEC);
    k_scan1<<<2 * nbN, SB>>>();
    k_scan2<<<2, 256>>>(nbN);
    k_scan3<<<2 * nbN, SB>>>();
    k_place<<<gEC + gED, T>>>(eic, eid, gEC);
    k_fill<<<2 * gN, T>>>(gN);
    k_z_first<<<gN, T>>>(x, W1l);

    // ---- fused layers: gather + node + BN + next-z in one kernel each ----
    // layer 1: conv1 + bn1 (next payload W4l)
    k_layer_first<<<gN, T>>>(x, W1r, g1, b1, W4l, ph);
    // layer 2: conv4 + bn2 (next W2l)
    k_layer<<<gN, T>>>(prc, pcc, pcsrc, W4r, g2, b2, W2l, ph, 1, 1);
    // layer 3 (destination edges): conv2 + bn3 (next W3l)
    k_layer<<<gN, T>>>(prd, pcd, pcsrd, W2r, g3, b3, W3l, ph, 2, 1);
    // layer 4: conv3 + bn4 (next W3l)
    k_layer<<<gN, T>>>(prc, pcc, pcsrc, W3r, g4, b4, W3l, ph, 3, 1);
    // layer 5: conv3 + bn4 -> d_out
    k_layer<<<gN, T>>>(prc, pcc, pcsrc, W3r, g4, b4, nullptr, out, 4, 0);
}